// round 4
// baseline (speedup 1.0000x reference)
#include <cuda_runtime.h>
#include <cuda_bf16.h>

// SHEmbed: out[b, :] = clip( sum_j  B_j(ray_dir[b]) * sh_data[y[b], x[b], j, :], 0, 1 )
// L = 3 -> 16 basis functions. sh_data: [1024, 1024, 16, 3] f32 (48 floats = 192 B per record,
// 16-byte aligned) -> 12x float4 gather per ray, all issued up front (MLP ~ 12).

#define SH_W 1024

__global__ __launch_bounds__(256)
void SHEmbed_kernel(const int* __restrict__ yi,
                    const int* __restrict__ xi,
                    const float* __restrict__ dirs,
                    const float4* __restrict__ sh,   // sh_data viewed as float4[H*W*12]
                    float* __restrict__ out,
                    int n)
{
    int i = blockIdx.x * blockDim.x + threadIdx.x;
    if (i >= n) return;

    // Issue all independent loads first: index pair, direction, then the 12-wide gather.
    int yv = __ldg(yi + i);
    int xv = __ldg(xi + i);
    float dx = __ldg(dirs + 3 * i + 0);
    float dy = __ldg(dirs + 3 * i + 1);
    float dz = __ldg(dirs + 3 * i + 2);

    unsigned base = ((unsigned)yv * SH_W + (unsigned)xv) * 12u;  // float4 units

    float4 v0  = __ldg(sh + base + 0);
    float4 v1  = __ldg(sh + base + 1);
    float4 v2  = __ldg(sh + base + 2);
    float4 v3  = __ldg(sh + base + 3);
    float4 v4  = __ldg(sh + base + 4);
    float4 v5  = __ldg(sh + base + 5);
    float4 v6  = __ldg(sh + base + 6);
    float4 v7  = __ldg(sh + base + 7);
    float4 v8  = __ldg(sh + base + 8);
    float4 v9  = __ldg(sh + base + 9);
    float4 v10 = __ldg(sh + base + 10);
    float4 v11 = __ldg(sh + base + 11);

    // ---- ray direction -> unit vector (overlaps gather latency) ----
    float rinv = rsqrtf(dx * dx + dy * dy + dz * dz + 1e-28f);
    float nx = dx * rinv, ny = dy * rinv, nz = dz * rinv;

    // ---- closed-form degree-3 real SH basis (matches reference sign convention) ----
    float xx = nx * nx, yy = ny * ny, zz = nz * nz;
    float xy = nx * ny, yz = ny * nz, xz = nx * nz;

    float b0  =  0.28209479177387814f;
    float b1  = -0.4886025119029199f * ny;
    float b2  =  0.4886025119029199f * nz;
    float b3  = -0.4886025119029199f * nx;
    float b4  =  1.0925484305920792f * xy;
    float b5  = -1.0925484305920792f * yz;
    float b6  =  0.31539156525252005f * (3.0f * zz - 1.0f);
    float b7  = -1.0925484305920792f * xz;
    float b8  =  0.5462742152960396f * (xx - yy);
    float b9  = -0.5900435899266435f * ny * (3.0f * xx - yy);
    float b10 =  2.890611442640554f  * xy * nz;
    float b11 = -0.4570457994644658f * ny * (5.0f * zz - 1.0f);
    float b12 =  0.3731763325901154f * nz * (5.0f * zz - 3.0f);
    float b13 = -0.4570457994644658f * nx * (5.0f * zz - 1.0f);
    float b14 =  1.4453057213202769f * nz * (xx - yy);
    float b15 = -0.5900435899266435f * nx * (xx - 3.0f * yy);

    // ---- dot: 16 coeff triples (r,g,b interleaved, stride 3 floats) ----
    // float4 layout: v0 = {c0r,c0g,c0b, c1r}, v1 = {c1g,c1b, c2r,c2g}, v2 = {c2b, c3r,c3g,c3b}, ...
    float cr, cg, cb;
    cr  = b0  * v0.x;   cg  = b0  * v0.y;   cb  = b0  * v0.z;
    cr += b1  * v0.w;   cg += b1  * v1.x;   cb += b1  * v1.y;
    cr += b2  * v1.z;   cg += b2  * v1.w;   cb += b2  * v2.x;
    cr += b3  * v2.y;   cg += b3  * v2.z;   cb += b3  * v2.w;

    cr += b4  * v3.x;   cg += b4  * v3.y;   cb += b4  * v3.z;
    cr += b5  * v3.w;   cg += b5  * v4.x;   cb += b5  * v4.y;
    cr += b6  * v4.z;   cg += b6  * v4.w;   cb += b6  * v5.x;
    cr += b7  * v5.y;   cg += b7  * v5.z;   cb += b7  * v5.w;

    cr += b8  * v6.x;   cg += b8  * v6.y;   cb += b8  * v6.z;
    cr += b9  * v6.w;   cg += b9  * v7.x;   cb += b9  * v7.y;
    cr += b10 * v7.z;   cg += b10 * v7.w;   cb += b10 * v8.x;
    cr += b11 * v8.y;   cg += b11 * v8.z;   cb += b11 * v8.w;

    cr += b12 * v9.x;   cg += b12 * v9.y;   cb += b12 * v9.z;
    cr += b13 * v9.w;   cg += b13 * v10.x;  cb += b13 * v10.y;
    cr += b14 * v10.z;  cg += b14 * v10.w;  cb += b14 * v11.x;
    cr += b15 * v11.y;  cg += b15 * v11.z;  cb += b15 * v11.w;

    // ---- clamp + coalesced store ----
    out[3 * i + 0] = fminf(fmaxf(cr, 0.0f), 1.0f);
    out[3 * i + 1] = fminf(fmaxf(cg, 0.0f), 1.0f);
    out[3 * i + 2] = fminf(fmaxf(cb, 0.0f), 1.0f);
}

extern "C" void kernel_launch(void* const* d_in, const int* in_sizes, int n_in,
                              void* d_out, int out_size)
{
    const int*    y    = (const int*)d_in[0];
    const int*    x    = (const int*)d_in[1];
    const float*  dirs = (const float*)d_in[2];
    const float4* sh   = (const float4*)d_in[3];
    float*        out  = (float*)d_out;

    int n = in_sizes[0];
    int threads = 256;
    int blocks = (n + threads - 1) / threads;
    SHEmbed_kernel<<<blocks, threads>>>(y, x, dirs, sh, out, n);
}

// round 6
// speedup vs baseline: 1.1548x; 1.1548x over previous
#include <cuda_runtime.h>
#include <cuda_bf16.h>

// SHEmbed, cooperative quad-gather version.
// 4 lanes per ray: lane p loads 48B chunk (float4 3p..3p+2) of the 192B record,
// computes partial dot over coefficients 4p..4p+3, quad-butterfly-reduces,
// lane p<3 writes output channel p.

#define SH_W 1024

__global__ __launch_bounds__(256)
void SHEmbed_kernel(const int* __restrict__ yi,
                    const int* __restrict__ xi,
                    const float* __restrict__ dirs,
                    const float4* __restrict__ sh,   // sh_data viewed as float4[H*W*12]
                    float* __restrict__ out,
                    int n)
{
    int t = blockIdx.x * blockDim.x + threadIdx.x;
    int r = t >> 2;          // ray index
    int p = t & 3;           // quad lane: coefficient group 4p..4p+3
    if (r >= n) return;

    // ---- issue all loads up front ----
    int yv = __ldg(yi + r);
    int xv = __ldg(xi + r);
    float dx = __ldg(dirs + 3 * r + 0);
    float dy = __ldg(dirs + 3 * r + 1);
    float dz = __ldg(dirs + 3 * r + 2);

    unsigned base = ((unsigned)yv * SH_W + (unsigned)xv) * 12u + (unsigned)(3 * p);
    float4 v0 = __ldg(sh + base + 0);
    float4 v1 = __ldg(sh + base + 1);
    float4 v2 = __ldg(sh + base + 2);

    // ---- unit direction (overlaps gather latency) ----
    float rinv = rsqrtf(dx * dx + dy * dy + dz * dz + 1e-28f);
    float nx = dx * rinv, ny = dy * rinv, nz = dz * rinv;

    float xx = nx * nx, yy = ny * ny, zz = nz * nz;
    float xy = nx * ny, yz = ny * nz, xz = nx * nz;

    // ---- basis weights for this lane's 4 coefficients ----
    float w0, w1, w2, w3;
    switch (p) {
    case 0:
        w0 =  0.28209479177387814f;
        w1 = -0.4886025119029199f * ny;
        w2 =  0.4886025119029199f * nz;
        w3 = -0.4886025119029199f * nx;
        break;
    case 1:
        w0 =  1.0925484305920792f * xy;
        w1 = -1.0925484305920792f * yz;
        w2 =  0.31539156525252005f * (3.0f * zz - 1.0f);
        w3 = -1.0925484305920792f * xz;
        break;
    case 2:
        w0 =  0.5462742152960396f * (xx - yy);
        w1 = -0.5900435899266435f * ny * (3.0f * xx - yy);
        w2 =  2.890611442640554f  * xy * nz;
        w3 = -0.4570457994644658f * ny * (5.0f * zz - 1.0f);
        break;
    default:
        w0 =  0.3731763325901154f * nz * (5.0f * zz - 3.0f);
        w1 = -0.4570457994644658f * nx * (5.0f * zz - 1.0f);
        w2 =  1.4453057213202769f * nz * (xx - yy);
        w3 = -0.5900435899266435f * nx * (xx - 3.0f * yy);
        break;
    }

    // ---- partial dot over this lane's 4 coefficient triples ----
    // chunk layout (floats 12p..12p+11):
    //   v0 = {c0r,c0g,c0b, c1r}, v1 = {c1g,c1b, c2r,c2g}, v2 = {c2b, c3r,c3g,c3b}
    float cr = w0 * v0.x + w1 * v0.w + w2 * v1.z + w3 * v2.y;
    float cg = w0 * v0.y + w1 * v1.x + w2 * v1.w + w3 * v2.z;
    float cb = w0 * v0.z + w1 * v1.y + w2 * v2.x + w3 * v2.w;

    // ---- quad reduction (lanes p=0..3 of the same ray) ----
    const unsigned m = 0xffffffffu;
    cr += __shfl_xor_sync(m, cr, 1);
    cr += __shfl_xor_sync(m, cr, 2);
    cg += __shfl_xor_sync(m, cg, 1);
    cg += __shfl_xor_sync(m, cg, 2);
    cb += __shfl_xor_sync(m, cb, 1);
    cb += __shfl_xor_sync(m, cb, 2);

    // ---- clamp + store: lane p<3 writes channel p ----
    if (p < 3) {
        float v = (p == 0) ? cr : (p == 1) ? cg : cb;
        out[3 * r + p] = fminf(fmaxf(v, 0.0f), 1.0f);
    }
}

extern "C" void kernel_launch(void* const* d_in, const int* in_sizes, int n_in,
                              void* d_out, int out_size)
{
    const int*    y    = (const int*)d_in[0];
    const int*    x    = (const int*)d_in[1];
    const float*  dirs = (const float*)d_in[2];
    const float4* sh   = (const float4*)d_in[3];
    float*        out  = (float*)d_out;

    int n = in_sizes[0];
    int threads = 256;
    long long total = 4LL * n;
    int blocks = (int)((total + threads - 1) / threads);
    SHEmbed_kernel<<<blocks, threads>>>(y, x, dirs, sh, out, n);
}